// round 6
// baseline (speedup 1.0000x reference)
#include <cuda_runtime.h>

#define B_ 64
#define N_ 2048
#define D_ 256
#define EPS_ 1e-5f

#define VEC_PER_B   (N_ * D_ / 4)        // 131072 float4 per batch
#define VEC_PER_ROW (D_ / 4)             // 64 float4 per row
#define TOTAL_VEC   (B_ * VEC_PER_B)     // 8388608 float4

#define GRID_       512                  // persistent blocks (<=4/SM, always resident)
#define THREADS_    256
#define CHUNK_VEC   2048                 // float4 per phase-1 chunk (32KB)
#define SEGS_       (VEC_PER_B / CHUNK_VEC)   // 64 chunks per batch
#define NCHUNK      (B_ * SEGS_)              // 4096 chunks total

// Per-chunk partials, written unconditionally (zeros for masked chunks).
__device__ float    g_psum[NCHUNK];
__device__ float    g_psumsq[NCHUNK];
__device__ unsigned g_arrive;

// ---------------------------------------------------------------- reset barrier counter
__global__ void sn_reset_kernel() {
    if (threadIdx.x == 0) g_arrive = 0u;
}

// ---------------------------------------------------------------- fused: reduce + barrier + finalize + normalize
__global__ void __launch_bounds__(THREADS_, 4)
sn_fused_kernel(const float4* __restrict__ x, const int* __restrict__ lengths,
                const float4* __restrict__ w, const float4* __restrict__ bias,
                float4* __restrict__ out) {
    const int tid = threadIdx.x;
    const int bid = blockIdx.x;
    const int lane = tid & 31;
    const int wid  = tid >> 5;

    __shared__ float sh_s[THREADS_ / 32];
    __shared__ float sh_q[THREADS_ / 32];
    __shared__ float sh_mean[B_];
    __shared__ float sh_inv[B_];

    // ================= phase 1: grid-stride over 4096 chunks, per-chunk partials
    for (int chunk = bid; chunk < NCHUNK; chunk += GRID_) {
        int b   = chunk >> 6;            // / SEGS_ (64)
        int seg = chunk & (SEGS_ - 1);
        int len = __ldg(&lengths[b]);
        int valid_vec = len * VEC_PER_ROW;
        int base = seg * CHUNK_VEC;

        float s = 0.0f, sq = 0.0f;
        const float4* xv = x + (size_t)b * VEC_PER_B;

        if (base + CHUNK_VEC <= valid_vec) {
            // fully valid chunk: unguarded, front-batched LDG.128
#pragma unroll
            for (int k = 0; k < CHUNK_VEC / THREADS_; ++k) {   // 8 iters
                float4 v = xv[base + tid + k * THREADS_];
                s  += (v.x + v.y) + (v.z + v.w);
                sq += (v.x * v.x + v.y * v.y) + (v.z * v.z + v.w * v.w);
            }
        } else if (base < valid_vec) {
#pragma unroll
            for (int k = 0; k < CHUNK_VEC / THREADS_; ++k) {
                int i = base + tid + k * THREADS_;
                if (i < valid_vec) {
                    float4 v = xv[i];
                    s  += (v.x + v.y) + (v.z + v.w);
                    sq += (v.x * v.x + v.y * v.y) + (v.z * v.z + v.w * v.w);
                }
            }
        }
        // block reduce
#pragma unroll
        for (int off = 16; off > 0; off >>= 1) {
            s  += __shfl_xor_sync(0xFFFFFFFFu, s,  off);
            sq += __shfl_xor_sync(0xFFFFFFFFu, sq, off);
        }
        if (lane == 0) { sh_s[wid] = s; sh_q[wid] = sq; }
        __syncthreads();
        if (wid == 0) {
            s  = (lane < THREADS_ / 32) ? sh_s[lane] : 0.0f;
            sq = (lane < THREADS_ / 32) ? sh_q[lane] : 0.0f;
#pragma unroll
            for (int off = 4; off > 0; off >>= 1) {
                s  += __shfl_xor_sync(0xFFFFFFFFu, s,  off);
                sq += __shfl_xor_sync(0xFFFFFFFFu, sq, off);
            }
            if (lane == 0) {
                g_psum[chunk]   = s;
                g_psumsq[chunk] = sq;
            }
        }
        __syncthreads();   // protect sh_s/sh_q reuse next chunk
    }

    // ================= grid barrier (all 512 blocks resident by construction)
    __syncthreads();
    if (tid == 0) {
        __threadfence();                       // partial stores visible device-wide
        atomicAdd(&g_arrive, 1u);
        volatile unsigned* p = &g_arrive;
        while (*p < (unsigned)GRID_) { }
    }
    __syncthreads();
    __threadfence();

    // ================= finalize: every block computes all 64 means/rstds
    {
        int b2   = tid >> 2;                   // 4 threads per batch
        int part = tid & 3;                    // each sums 16 of 64 partials
        float s = 0.0f, sq = 0.0f;
#pragma unroll
        for (int i = 0; i < SEGS_ / 4; ++i) {
            int c = b2 * SEGS_ + part * (SEGS_ / 4) + i;
            s  += g_psum[c];
            sq += g_psumsq[c];
        }
        s  += __shfl_xor_sync(0xFFFFFFFFu, s,  1);
        s  += __shfl_xor_sync(0xFFFFFFFFu, s,  2);
        sq += __shfl_xor_sync(0xFFFFFFFFu, sq, 1);
        sq += __shfl_xor_sync(0xFFFFFFFFu, sq, 2);
        if (part == 0) {
            float denom = (float)__ldg(&lengths[b2]) * (float)D_;
            float mean  = s / denom;
            float var   = sq / denom - mean * mean;
            var = fmaxf(var, 0.0f);
            sh_mean[b2] = mean;
            sh_inv[b2]  = 1.0f / (sqrtf(var) + EPS_);
        }
        __syncthreads();
    }

    // ================= phase 2: normalize + affine + mask (x hot in L2)
    const float4 z4 = make_float4(0.0f, 0.0f, 0.0f, 0.0f);
    for (int idx = bid * THREADS_ + tid; idx < TOTAL_VEC; idx += GRID_ * THREADS_) {
        int b = idx >> 17;                     // / VEC_PER_B
        int r = idx & (VEC_PER_B - 1);
        int n = r >> 6;                        // / VEC_PER_ROW
        int len = __ldg(&lengths[b]);

        if (n >= len) {
            __stcs(&out[idx], z4);             // evict-first: keep L2 for x
            continue;
        }
        float4 v = x[idx];
        float m   = sh_mean[b];
        float inv = sh_inv[b];
        int dv = r & (VEC_PER_ROW - 1);
        float4 wv = __ldg(&w[dv]);
        float4 bv = __ldg(&bias[dv]);

        float4 o;
        o.x = fmaf((v.x - m) * inv, wv.x, bv.x);
        o.y = fmaf((v.y - m) * inv, wv.y, bv.y);
        o.z = fmaf((v.z - m) * inv, wv.z, bv.z);
        o.w = fmaf((v.w - m) * inv, wv.w, bv.w);
        __stcs(&out[idx], o);
    }
}

// ---------------------------------------------------------------- launch
extern "C" void kernel_launch(void* const* d_in, const int* in_sizes, int n_in,
                              void* d_out, int out_size) {
    const float* x       = (const float*)d_in[0];
    const int*   lengths = (const int*)  d_in[1];
    const float* weights = (const float*)d_in[2];
    const float* biases  = (const float*)d_in[3];
    float*       out     = (float*)d_out;

    sn_reset_kernel<<<1, 32>>>();
    sn_fused_kernel<<<GRID_, THREADS_>>>(
        (const float4*)x, lengths,
        (const float4*)weights, (const float4*)biases,
        (float4*)out);
}